// round 1
// baseline (speedup 1.0000x reference)
#include <cuda_runtime.h>

#define BB 2
#define LL 384
#define HH 8
#define DD 64
#define HIDN 512
#define BH (BB*HH)          // 16
#define MROWS (BB*LL)       // 768
#define X_ELEMS (MROWS*HIDN)    // 393216
#define A_ELEMS (BH*LL*LL)      // 2359296

// -------- scratch (no dynamic allocation allowed) --------
__device__ float g_Q [BH*LL*DD];
__device__ float g_K [BH*LL*DD];
__device__ float g_V [BH*LL*DD];
__device__ float g_tQ[BH*LL*DD];
__device__ float g_tK[BH*LL*DD];
__device__ float g_X [X_ELEMS];
__device__ float g_attn[A_ELEMS];   // fallback if out buffer holds only x

__device__ __forceinline__ float tanh_fast(float x) {
    float y;
    asm("tanh.approx.f32 %0, %1;" : "=f"(y) : "f"(x));
    return y;
}

// out[m,n] = X[m,:] . W[n,:] + bias[n]   (torch Linear: X @ W^T + b)
// head_major=1 -> write to [b,h,l,d] layout; else plain [m, HIDN]
__global__ void __launch_bounds__(256) gemm_xwT(
    const float* __restrict__ X, const float* __restrict__ W,
    const float* __restrict__ bias, float* __restrict__ out, int head_major)
{
    __shared__ float As[16][65];
    __shared__ float Bs[16][65];
    int tx = threadIdx.x, ty = threadIdx.y;
    int tid = ty * 16 + tx;
    int m0 = blockIdx.y * 64, n0 = blockIdx.x * 64;
    float acc[4][4] = {};
    for (int kk = 0; kk < HIDN; kk += 16) {
#pragma unroll
        for (int i = 0; i < 4; i++) {
            int idx = tid + i * 256;        // 0..1023
            int ci = idx & 15, ri = idx >> 4;
            As[ci][ri] = X[(m0 + ri) * HIDN + kk + ci];
            Bs[ci][ri] = W[(n0 + ri) * HIDN + kk + ci];
        }
        __syncthreads();
#pragma unroll
        for (int c = 0; c < 16; c++) {
            float a[4], b[4];
#pragma unroll
            for (int i = 0; i < 4; i++) a[i] = As[c][ty * 4 + i];
#pragma unroll
            for (int j = 0; j < 4; j++) b[j] = Bs[c][tx * 4 + j];
#pragma unroll
            for (int i = 0; i < 4; i++)
#pragma unroll
                for (int j = 0; j < 4; j++)
                    acc[i][j] = fmaf(a[i], b[j], acc[i][j]);
        }
        __syncthreads();
    }
#pragma unroll
    for (int i = 0; i < 4; i++) {
        int m = m0 + ty * 4 + i;
        int b = m / LL, l = m % LL;
#pragma unroll
        for (int j = 0; j < 4; j++) {
            int n = n0 + tx * 4 + j;
            float v = acc[i][j] + __ldg(&bias[n]);
            if (head_major) {
                int h = n >> 6, d = n & 63;
                out[(((b * HH + h) * LL) + l) * DD + d] = v;
            } else {
                out[m * HIDN + n] = v;
            }
        }
    }
}

// tQ = Q @ W1^T + b1 ; tK = K @ W2^T + b2  (per-head D x D, same W for all heads)
__global__ void __launch_bounds__(256) head_proj(
    const float* __restrict__ W1, const float* __restrict__ b1,
    const float* __restrict__ W2, const float* __restrict__ b2)
{
    int sel = blockIdx.z;
    const float* in  = sel ? g_K  : g_Q;
    float*       op  = sel ? g_tK : g_tQ;
    const float* W   = sel ? W2 : W1;
    const float* bb  = sel ? b2 : b1;
    __shared__ float Ws[DD][DD + 1];
    __shared__ float Qs[DD][DD + 1];
    int tx = threadIdx.x, ty = threadIdx.y;  // (64,4)
    int tid = ty * 64 + tx;
    int bh = blockIdx.y;
    int l0 = blockIdx.x * 64;
#pragma unroll
    for (int i = 0; i < 16; i++) {
        int idx = tid + i * 256;             // 0..4095
        Ws[idx >> 6][idx & 63] = W[idx];
        Qs[idx >> 6][idx & 63] = in[(bh * LL + l0) * DD + idx];
    }
    __syncthreads();
    float acc[16];
    float bv = __ldg(&bb[tx]);
#pragma unroll
    for (int r = 0; r < 16; r++) acc[r] = bv;
    for (int c = 0; c < DD; c++) {
        float w = Ws[tx][c];
#pragma unroll
        for (int r = 0; r < 16; r++)
            acc[r] = fmaf(Qs[ty + r * 4][c], w, acc[r]);
    }
#pragma unroll
    for (int r = 0; r < 16; r++)
        op[(bh * LL + l0 + ty + r * 4) * DD + tx] = acc[r];
}

// energy[q,k] = sum_d vw[d]*tanh(tQ[q,d]+tK[k,d]) ; mask ; softmax over k ; write attn
// one block = 16 q-rows of one (b,h); full k range in shared -> fused softmax
__global__ void __launch_bounds__(256) energy_softmax(
    const int* __restrict__ mask, const float* __restrict__ vw,
    float* __restrict__ attn)
{
    __shared__ float sQ[16][DD + 1];
    __shared__ float sK[DD][DD + 1];
    __shared__ float sE[16][LL + 1];
    __shared__ float sVW[DD];
    int tx = threadIdx.x, ty = threadIdx.y;  // (16,16)
    int tid = ty * 16 + tx;
    int bh = blockIdx.y;
    int b  = bh >> 3;
    int q0 = blockIdx.x * 16;
    if (tid < DD) sVW[tid] = vw[tid];
#pragma unroll
    for (int i = 0; i < 4; i++) {
        int idx = tid + i * 256;             // 0..1023
        sQ[idx >> 6][idx & 63] = g_tQ[(bh * LL + q0) * DD + idx];
    }
    __syncthreads();
    for (int kc = 0; kc < LL; kc += DD) {
#pragma unroll
        for (int i = 0; i < 16; i++) {
            int idx = tid + i * 256;         // 0..4095
            sK[idx >> 6][idx & 63] = g_tK[(bh * LL + kc) * DD + idx];
        }
        __syncthreads();
        float a0 = 0.f, a1 = 0.f, a2 = 0.f, a3 = 0.f;
#pragma unroll
        for (int d = 0; d < DD; d++) {
            float qv = sQ[ty][d];
            float w  = sVW[d];
            a0 = fmaf(w, tanh_fast(qv + sK[tx     ][d]), a0);
            a1 = fmaf(w, tanh_fast(qv + sK[tx + 16][d]), a1);
            a2 = fmaf(w, tanh_fast(qv + sK[tx + 32][d]), a2);
            a3 = fmaf(w, tanh_fast(qv + sK[tx + 48][d]), a3);
        }
        sE[ty][kc + tx]      = a0;
        sE[ty][kc + tx + 16] = a1;
        sE[ty][kc + tx + 32] = a2;
        sE[ty][kc + tx + 48] = a3;
        __syncthreads();
    }
    // softmax over 384 cols; row ty handled by 16 lanes (half-warp)
    float ev[24];
    float mx = -3.0e38f;
#pragma unroll
    for (int i = 0; i < 24; i++) {
        int j = tx + i * 16;
        float e = sE[ty][j];
        if (__ldg(&mask[b * LL + j]) == 0) e = -1e10f;
        ev[i] = e;
        mx = fmaxf(mx, e);
    }
#pragma unroll
    for (int o = 8; o > 0; o >>= 1) mx = fmaxf(mx, __shfl_xor_sync(0xffffffffu, mx, o));
    float sum = 0.f;
#pragma unroll
    for (int i = 0; i < 24; i++) { ev[i] = __expf(ev[i] - mx); sum += ev[i]; }
#pragma unroll
    for (int o = 8; o > 0; o >>= 1) sum += __shfl_xor_sync(0xffffffffu, sum, o);
    float inv = __frcp_rn(sum);
#pragma unroll
    for (int i = 0; i < 24; i++) sE[ty][tx + i * 16] = ev[i] * inv;
    __syncthreads();
    // coalesced store of the 16 x 384 attention tile
    float* dst = attn + (bh * LL + q0) * LL;
    for (int idx = tid; idx < 16 * LL; idx += 256) {
        int r = idx / LL, j = idx - r * LL;
        dst[r * LL + j] = sE[r][j];
    }
}

// x[bh,q,d] = sum_k attn[bh,q,k] * V[bh,k,d] ; write concat-head layout
__global__ void __launch_bounds__(256) av_kernel(const float* __restrict__ attn)
{
    __shared__ float sA[DD][DD + 1];
    __shared__ float sV[DD][DD + 1];
    int tx = threadIdx.x, ty = threadIdx.y;  // (64,4)
    int tid = ty * 64 + tx;
    int bh = blockIdx.y;
    int b = bh >> 3, h = bh & 7;
    int q0 = blockIdx.x * 64;
    float acc[16] = {};
    for (int kc = 0; kc < LL; kc += 64) {
#pragma unroll
        for (int i = 0; i < 16; i++) {
            int idx = tid + i * 256;
            int r = idx >> 6, c = idx & 63;
            sA[r][c] = attn[(bh * LL + q0 + r) * LL + kc + c];
            sV[r][c] = g_V[(bh * LL + kc + r) * DD + c];
        }
        __syncthreads();
        for (int k = 0; k < 64; k++) {
            float v = sV[k][tx];
#pragma unroll
            for (int r = 0; r < 16; r++)
                acc[r] = fmaf(sA[ty + r * 4][k], v, acc[r]);
        }
        __syncthreads();
    }
#pragma unroll
    for (int r = 0; r < 16; r++) {
        int q = q0 + ty + r * 4;
        g_X[(b * LL + q) * HIDN + h * DD + tx] = acc[r];
    }
}

extern "C" void kernel_launch(void* const* d_in, const int* in_sizes, int n_in,
                              void* d_out, int out_size)
{
    const float* query = (const float*)d_in[0];
    const float* key_  = (const float*)d_in[1];
    const float* value = (const float*)d_in[2];
    const int*   mask  = (const int*)  d_in[3];
    const float* Wq = (const float*)d_in[4];
    const float* bq = (const float*)d_in[5];
    const float* Wk = (const float*)d_in[6];
    const float* bk = (const float*)d_in[7];
    const float* Wv = (const float*)d_in[8];
    const float* bv = (const float*)d_in[9];
    const float* Wo = (const float*)d_in[10];
    const float* bo = (const float*)d_in[11];
    const float* W1 = (const float*)d_in[12];
    const float* b1 = (const float*)d_in[13];
    const float* W2 = (const float*)d_in[14];
    const float* b2 = (const float*)d_in[15];
    const float* vw = (const float*)d_in[16];
    (void)d_in[17]; // vb cancels exactly in softmax; energy is never an output
    (void)in_sizes; (void)n_in;

    float* out = (float*)d_out;

    float *gQ, *gK, *gV, *gX, *gA;
    cudaGetSymbolAddress((void**)&gQ, g_Q);
    cudaGetSymbolAddress((void**)&gK, g_K);
    cudaGetSymbolAddress((void**)&gV, g_V);
    cudaGetSymbolAddress((void**)&gX, g_X);
    cudaGetSymbolAddress((void**)&gA, g_attn);

    // attention goes directly into the output buffer if it is part of the output
    float* attn_dst = (out_size >= X_ELEMS + A_ELEMS) ? (out + X_ELEMS) : gA;

    dim3 gB(16, 16);
    dim3 gG(HIDN / 64, MROWS / 64);   // (8, 12)

    gemm_xwT<<<gG, gB>>>(query, Wq, bq, gQ, 1);
    gemm_xwT<<<gG, gB>>>(key_,  Wk, bk, gK, 1);
    gemm_xwT<<<gG, gB>>>(value, Wv, bv, gV, 1);

    head_proj<<<dim3(LL / 64, BH, 2), dim3(64, 4)>>>(W1, b1, W2, b2);

    energy_softmax<<<dim3(LL / 16, BH), dim3(16, 16)>>>(mask, vw, attn_dst);

    av_kernel<<<dim3(LL / 64, BH), dim3(64, 4)>>>(attn_dst);

    gemm_xwT<<<gG, gB>>>(gX, Wo, bo, out, 0);
}